// round 2
// baseline (speedup 1.0000x reference)
#include <cuda_runtime.h>

// Problem constants (fixed by the reference)
#define M_ITEMS 100000
#define N_USERS 50000
#define DIM     64
#define NB      (M_ITEMS * DIM)   // 6,400,000 floats
#define NU      (N_USERS * DIM)   // 3,200,000 floats

// Static device scratch (no allocations allowed)
__device__ float g_bufA[NB];   // layer ping (written by layer 1)
__device__ float g_bufB[NB];   // layer pong (written by layers 0 and 2)
__device__ float g_sum[NB];    // running sum of embs (mean folded later as 0.25)
__device__ float g_users[NU];  // all_users (exact, 0.25 folded into ui spmm)

// Vector reduction-add to global (sm_90+). One instruction, 16B.
__device__ __forceinline__ void red_add_f4(float4* addr, float4 v) {
    asm volatile("red.global.add.v4.f32 [%0], {%1, %2, %3, %4};"
                 :: "l"(addr), "f"(v.x), "f"(v.y), "f"(v.z), "f"(v.w)
                 : "memory");
}

// init: g_sum = item_emb, g_bufA = g_bufB = 0, g_users = 0
__global__ void k_init(const float* __restrict__ emb) {
    int i = blockIdx.x * blockDim.x + threadIdx.x;
    if (i < NB) {
        g_sum[i]  = emb[i];
        g_bufA[i] = 0.0f;
        g_bufB[i] = 0.0f;
    }
    if (i < NU) g_users[i] = 0.0f;
}

// item-item SpMM layer: y[src] += (val * att[layer]) * x[dst]
// 16 lanes per edge, one float4 per lane (64 floats per row).
__global__ void k_spmm_ii(const int* __restrict__ src,
                          const int* __restrict__ dst,
                          const float* __restrict__ val,
                          const float* __restrict__ att,
                          const float* __restrict__ x,  // layer input
                          float* __restrict__ y,        // layer output (pre-zeroed)
                          int layer, int nedges) {
    long t = (long)blockIdx.x * blockDim.x + threadIdx.x;
    int e    = (int)(t >> 4);
    int lane = (int)(t & 15);
    if (e >= nedges) return;

    int   s = __ldg(src + e);
    int   d = __ldg(dst + e);
    float v = __ldg(val + e) * __ldg(att + layer);

    float4 xv = __ldg((const float4*)x + (long)d * 16 + lane);
    float4 r  = make_float4(xv.x * v, xv.y * v, xv.z * v, xv.w * v);
    red_add_f4((float4*)y + (long)s * 16 + lane, r);
}

// After a layer wrote 'just': sum += just, zero 'other' (the next layer's output)
__global__ void k_accum(const float* __restrict__ just, float* __restrict__ other) {
    int i = blockIdx.x * blockDim.x + threadIdx.x;
    if (i >= NB) return;
    g_sum[i] += just[i];
    other[i] = 0.0f;
}

// user-item SpMM: g_users[src] += (val * 0.25) * g_sum[dst]
// (0.25 = the mean over 4 layer embeddings, folded in here so g_users is exact)
__global__ void k_spmm_ui(const int* __restrict__ src,
                          const int* __restrict__ dst,
                          const float* __restrict__ val,
                          int nedges) {
    long t = (long)blockIdx.x * blockDim.x + threadIdx.x;
    int e    = (int)(t >> 4);
    int lane = (int)(t & 15);
    if (e >= nedges) return;

    int   s = __ldg(src + e);
    int   d = __ldg(dst + e);
    float v = __ldg(val + e) * 0.25f;

    float4 xv = __ldg((const float4*)g_sum + (long)d * 16 + lane);
    float4 r  = make_float4(xv.x * v, xv.y * v, xv.z * v, xv.w * v);
    red_add_f4((float4*)g_users + (long)s * 16 + lane, r);
}

// gamma[b] = dot(all_users[users[b]], all_items[items[b]])
//          = dot(g_users[u], 0.25 * g_sum[i])
// One warp per pair; each lane handles a float2 (64 floats / 32 lanes).
__global__ void k_dot(const int* __restrict__ users,
                      const int* __restrict__ items,
                      float* __restrict__ out, int nb) {
    int w    = (blockIdx.x * blockDim.x + threadIdx.x) >> 5;
    int lane = threadIdx.x & 31;
    if (w >= nb) return;

    int u = __ldg(users + w);
    int i = __ldg(items + w);

    float2 a = __ldg((const float2*)g_users + (long)u * 32 + lane);
    float2 b = __ldg((const float2*)g_sum   + (long)i * 32 + lane);
    float p = a.x * b.x + a.y * b.y;

    #pragma unroll
    for (int o = 16; o; o >>= 1) p += __shfl_xor_sync(0xFFFFFFFFu, p, o);

    if (lane == 0) out[w] = 0.25f * p;
}

extern "C" void kernel_launch(void* const* d_in, const int* in_sizes, int n_in,
                              void* d_out, int out_size) {
    const int*   users  = (const int*)d_in[0];
    const int*   items  = (const int*)d_in[1];
    const int*   ii_src = (const int*)d_in[2];
    const int*   ii_dst = (const int*)d_in[3];
    const float* ii_val = (const float*)d_in[4];
    const int*   ui_src = (const int*)d_in[5];
    const int*   ui_dst = (const int*)d_in[6];
    const float* ui_val = (const float*)d_in[7];
    const float* emb    = (const float*)d_in[8];
    const float* att    = (const float*)d_in[9];

    const int Eii = in_sizes[2];
    const int Eui = in_sizes[5];
    const int Bp  = in_sizes[0];

    const int TPB = 256;
    const int nbGrid = (NB + TPB - 1) / TPB;
    const int spmmGridII = (int)(((long)Eii * 16 + TPB - 1) / TPB);
    const int spmmGridUI = (int)(((long)Eui * 16 + TPB - 1) / TPB);

    // Resolve device-global scratch addresses (host-side symbol addresses of
    // __device__ arrays are directly usable as kernel args on all modern CUDA)
    float *bufA, *bufB;
    cudaGetSymbolAddress((void**)&bufA, g_bufA);
    cudaGetSymbolAddress((void**)&bufB, g_bufB);

    // init scratch
    k_init<<<nbGrid, TPB>>>(emb);

    // Layer 0: emb -> bufB ; accumulate into sum, zero bufA
    k_spmm_ii<<<spmmGridII, TPB>>>(ii_src, ii_dst, ii_val, att, emb,  bufB, 0, Eii);
    k_accum  <<<nbGrid, TPB>>>(bufB, bufA);
    // Layer 1: bufB -> bufA ; accumulate, zero bufB
    k_spmm_ii<<<spmmGridII, TPB>>>(ii_src, ii_dst, ii_val, att, bufB, bufA, 1, Eii);
    k_accum  <<<nbGrid, TPB>>>(bufA, bufB);
    // Layer 2: bufA -> bufB ; accumulate, zero bufA (harmless)
    k_spmm_ii<<<spmmGridII, TPB>>>(ii_src, ii_dst, ii_val, att, bufA, bufB, 2, Eii);
    k_accum  <<<nbGrid, TPB>>>(bufB, bufA);

    // user aggregation over the user-item graph (0.25 mean folded in)
    k_spmm_ui<<<spmmGridUI, TPB>>>(ui_src, ui_dst, ui_val, Eui);

    // final per-pair dots
    k_dot<<<(Bp * 32 + TPB - 1) / TPB, TPB>>>(users, items, (float*)d_out, Bp);
}

// round 3
// speedup vs baseline: 1.2948x; 1.2948x over previous
#include <cuda_runtime.h>

// Problem constants (fixed by the reference)
#define M_ITEMS 100000
#define N_USERS 50000
#define DIM     64
#define NB      (M_ITEMS * DIM)   // 6,400,000 floats
#define NU      (N_USERS * DIM)   // 3,200,000 floats
#define E_II_MAX 3200000

// Static device scratch (no allocations allowed)
__device__ float g_bufA[NB];            // layer ping
__device__ float g_bufB[NB];            // layer pong
__device__ float g_sum[NB];             // running sum of layer embeddings
__device__ float g_users[NU];           // all_users (0.25 mean folded into ui spmm)
__device__ int   g_cnt[M_ITEMS];        // per-row edge counts (histogram)
__device__ int   g_rowptr[M_ITEMS + 1]; // CSR row pointers
__device__ int   g_pos[M_ITEMS];        // scatter fill cursors
__device__ int   g_edst[E_II_MAX];      // CSR: permuted dst indices
__device__ float g_eval[E_II_MAX];      // CSR: permuted edge values
__device__ unsigned char g_uflag[N_USERS]; // batch-user membership flags

// Vector reduction-add to global (sm_90+)
__device__ __forceinline__ void red_add_f4(float4* addr, float4 v) {
    asm volatile("red.global.add.v4.f32 [%0], {%1, %2, %3, %4};"
                 :: "l"(addr), "f"(v.x), "f"(v.y), "f"(v.z), "f"(v.w)
                 : "memory");
}

// init: g_sum = emb, zero users/counters/flags
__global__ void k_init(const float* __restrict__ emb) {
    int i = blockIdx.x * blockDim.x + threadIdx.x;
    if (i < NB) g_sum[i] = emb[i];
    if (i < NU) g_users[i] = 0.0f;
    if (i < M_ITEMS) g_cnt[i] = 0;
    if (i < N_USERS) g_uflag[i] = 0;
}

// flag the users that appear in the batch
__global__ void k_flag(const int* __restrict__ users, int nb) {
    int i = blockIdx.x * blockDim.x + threadIdx.x;
    if (i < nb) g_uflag[users[i]] = 1;
}

// histogram of edge sources
__global__ void k_hist(const int* __restrict__ src, int n) {
    int e = blockIdx.x * blockDim.x + threadIdx.x;
    if (e < n) atomicAdd(&g_cnt[__ldg(src + e)], 1);
}

// exclusive scan over g_cnt -> g_rowptr (+ init g_pos). Single block, 1024 thr.
__global__ void k_scan() {
    __shared__ int s[1024];
    const int tid = threadIdx.x;
    const int CH = (M_ITEMS + 1023) / 1024;  // 98
    const int base = tid * CH;

    int local = 0;
    for (int i = 0; i < CH; i++) {
        int idx = base + i;
        if (idx < M_ITEMS) local += g_cnt[idx];
    }
    s[tid] = local;
    __syncthreads();
    // inclusive Hillis-Steele scan
    for (int off = 1; off < 1024; off <<= 1) {
        int v = (tid >= off) ? s[tid - off] : 0;
        __syncthreads();
        if (tid >= off) s[tid] += v;
        __syncthreads();
    }
    int run = (tid == 0) ? 0 : s[tid - 1];  // exclusive prefix of this chunk
    for (int i = 0; i < CH; i++) {
        int idx = base + i;
        if (idx < M_ITEMS) {
            g_rowptr[idx] = run;
            g_pos[idx]    = run;
            run += g_cnt[idx];
        }
    }
    if (tid == 1023) g_rowptr[M_ITEMS] = run;  // last chunk is empty; run == total
}

// scatter edges into CSR order
__global__ void k_scatter(const int* __restrict__ src, const int* __restrict__ dst,
                          const float* __restrict__ val, int n) {
    int e = blockIdx.x * blockDim.x + threadIdx.x;
    if (e >= n) return;
    int s = __ldg(src + e);
    int p = atomicAdd(&g_pos[s], 1);
    g_edst[p] = __ldg(dst + e);
    g_eval[p] = __ldg(val + e);
}

// Pull-based item-item SpMM layer, one warp per row, register accumulation.
// y[row] = att[layer] * sum_e val_e * x[dst_e];  g_sum[row] += y[row].
// If y == nullptr (last layer), skip the y store.
__global__ void k_spmm_pull(const float* __restrict__ x, float* __restrict__ y,
                            const float* __restrict__ att, int layer) {
    int row  = blockIdx.x * (blockDim.x >> 5) + (threadIdx.x >> 5);
    int lane = threadIdx.x & 31;
    if (row >= M_ITEMS) return;

    int beg = g_rowptr[row];
    int end = g_rowptr[row + 1];

    float2 acc = make_float2(0.0f, 0.0f);
    #pragma unroll 4
    for (int e = beg; e < end; e++) {
        int   d = __ldg(&g_edst[e]);   // warp-broadcast load
        float v = __ldg(&g_eval[e]);   // warp-broadcast load
        float2 xv = __ldg((const float2*)x + (long)d * 32 + lane);
        acc.x = fmaf(v, xv.x, acc.x);
        acc.y = fmaf(v, xv.y, acc.y);
    }
    float a = __ldg(att + layer);
    acc.x *= a; acc.y *= a;

    long o = (long)row * 32 + lane;
    if (y) ((float2*)y)[o] = acc;
    float2* sp = (float2*)g_sum + o;
    float2 sv = *sp;
    sv.x += acc.x; sv.y += acc.y;
    *sp = sv;
}

// user-item push SpMM, filtered to batch users:
// g_users[src] += (val * 0.25) * g_sum[dst]   (only if src is in the batch)
__global__ void k_spmm_ui(const int* __restrict__ src, const int* __restrict__ dst,
                          const float* __restrict__ val, int nedges) {
    long t = (long)blockIdx.x * blockDim.x + threadIdx.x;
    int e    = (int)(t >> 4);
    int lane = (int)(t & 15);
    if (e >= nedges) return;

    int s = __ldg(src + e);
    if (!g_uflag[s]) return;  // ~92% of edges exit here

    int   d = __ldg(dst + e);
    float v = __ldg(val + e) * 0.25f;

    float4 xv = __ldg((const float4*)g_sum + (long)d * 16 + lane);
    float4 r  = make_float4(xv.x * v, xv.y * v, xv.z * v, xv.w * v);
    red_add_f4((float4*)g_users + (long)s * 16 + lane, r);
}

// gamma[b] = dot(g_users[u], 0.25 * g_sum[i]); one warp per pair
__global__ void k_dot(const int* __restrict__ users, const int* __restrict__ items,
                      float* __restrict__ out, int nb) {
    int w    = (blockIdx.x * blockDim.x + threadIdx.x) >> 5;
    int lane = threadIdx.x & 31;
    if (w >= nb) return;

    int u = __ldg(users + w);
    int i = __ldg(items + w);

    float2 a = __ldg((const float2*)g_users + (long)u * 32 + lane);
    float2 b = __ldg((const float2*)g_sum   + (long)i * 32 + lane);
    float p = a.x * b.x + a.y * b.y;

    #pragma unroll
    for (int o = 16; o; o >>= 1) p += __shfl_xor_sync(0xFFFFFFFFu, p, o);

    if (lane == 0) out[w] = 0.25f * p;
}

extern "C" void kernel_launch(void* const* d_in, const int* in_sizes, int n_in,
                              void* d_out, int out_size) {
    const int*   users  = (const int*)d_in[0];
    const int*   items  = (const int*)d_in[1];
    const int*   ii_src = (const int*)d_in[2];
    const int*   ii_dst = (const int*)d_in[3];
    const float* ii_val = (const float*)d_in[4];
    const int*   ui_src = (const int*)d_in[5];
    const int*   ui_dst = (const int*)d_in[6];
    const float* ui_val = (const float*)d_in[7];
    const float* emb    = (const float*)d_in[8];
    const float* att    = (const float*)d_in[9];

    const int Eii = in_sizes[2];
    const int Eui = in_sizes[5];
    const int Bp  = in_sizes[0];

    const int TPB = 256;
    const int nbGrid   = (NB + TPB - 1) / TPB;
    const int eiiGrid  = (Eii + TPB - 1) / TPB;
    const int uiGrid   = (int)(((long)Eui * 16 + TPB - 1) / TPB);
    const int rowGrid  = (M_ITEMS + (TPB / 32) - 1) / (TPB / 32);

    float *bufA, *bufB;
    cudaGetSymbolAddress((void**)&bufA, g_bufA);
    cudaGetSymbolAddress((void**)&bufB, g_bufB);

    // init + batch-user flags
    k_init<<<nbGrid, TPB>>>(emb);
    k_flag<<<(Bp + TPB - 1) / TPB, TPB>>>(users, Bp);

    // build item-item CSR
    k_hist   <<<eiiGrid, TPB>>>(ii_src, Eii);
    k_scan   <<<1, 1024>>>();
    k_scatter<<<eiiGrid, TPB>>>(ii_src, ii_dst, ii_val, Eii);

    // 3 pull-based LightGCN layers (sum-accumulate fused into epilogue)
    k_spmm_pull<<<rowGrid, TPB>>>(emb,  bufA, att, 0);
    k_spmm_pull<<<rowGrid, TPB>>>(bufA, bufB, att, 1);
    k_spmm_pull<<<rowGrid, TPB>>>(bufB, nullptr, att, 2);

    // user aggregation, filtered to batch users (0.25 mean folded in)
    k_spmm_ui<<<uiGrid, TPB>>>(ui_src, ui_dst, ui_val, Eui);

    // final per-pair dots
    k_dot<<<(Bp * 32 + TPB - 1) / TPB, TPB>>>(users, items, (float*)d_out, Bp);
}

// round 4
// speedup vs baseline: 1.8369x; 1.4187x over previous
#include <cuda_runtime.h>

// Problem constants (fixed by the reference)
#define M_ITEMS 100000
#define N_USERS 50000
#define DIM     64
#define NB      (M_ITEMS * DIM)   // 6,400,000 floats
#define NU      (N_USERS * DIM)   // 3,200,000 floats
#define E_II_MAX 3200000

#define SCAN_CHUNK  1024
#define SCAN_BLOCKS ((M_ITEMS + SCAN_CHUNK - 1) / SCAN_CHUNK)  // 98

// Static device scratch (no allocations allowed)
__device__ float g_bufA[NB];            // layer ping
__device__ float g_bufB[NB];            // layer pong
__device__ float g_sum[NB];             // running sum of layer embeddings
__device__ float g_users[NU];           // all_users (0.25 mean folded into ui spmm)
__device__ int   g_cnt[M_ITEMS];        // per-row edge counts (histogram)
__device__ int   g_rowptr[M_ITEMS + 1]; // CSR row pointers
__device__ int   g_pos[M_ITEMS];        // scatter fill cursors
__device__ int2  g_epack[E_II_MAX];     // CSR: packed (dst, val-bits) per edge
__device__ int   g_part[SCAN_BLOCKS];   // scan partials
__device__ unsigned char g_uflag[N_USERS]; // batch-user membership flags

// Vector reduction-add to global (sm_90+)
__device__ __forceinline__ void red_add_f4(float4* addr, float4 v) {
    asm volatile("red.global.add.v4.f32 [%0], {%1, %2, %3, %4};"
                 :: "l"(addr), "f"(v.x), "f"(v.y), "f"(v.z), "f"(v.w)
                 : "memory");
}

// init: g_sum = emb, zero users/counters/flags
__global__ void k_init(const float* __restrict__ emb) {
    int i = blockIdx.x * blockDim.x + threadIdx.x;
    if (i < NB) g_sum[i] = emb[i];
    if (i < NU) g_users[i] = 0.0f;
    if (i < M_ITEMS) g_cnt[i] = 0;
    if (i < N_USERS) g_uflag[i] = 0;
}

// flag the users that appear in the batch
__global__ void k_flag(const int* __restrict__ users, int nb) {
    int i = blockIdx.x * blockDim.x + threadIdx.x;
    if (i < nb) g_uflag[users[i]] = 1;
}

// histogram of edge sources
__global__ void k_hist(const int* __restrict__ src, int n) {
    int e = blockIdx.x * blockDim.x + threadIdx.x;
    if (e < n) atomicAdd(&g_cnt[__ldg(src + e)], 1);
}

// ---- 3-pass parallel exclusive scan over g_cnt -> g_rowptr, g_pos ----

// pass 1: per-block (1024-element) sums, coalesced
__global__ void k_scan_part() {
    __shared__ int s[256];
    int tid  = threadIdx.x;
    int base = blockIdx.x * SCAN_CHUNK;
    int sum = 0;
    #pragma unroll
    for (int i = 0; i < 4; i++) {
        int idx = base + tid + i * 256;
        if (idx < M_ITEMS) sum += g_cnt[idx];
    }
    s[tid] = sum;
    __syncthreads();
    for (int off = 128; off; off >>= 1) {
        if (tid < off) s[tid] += s[tid + off];
        __syncthreads();
    }
    if (tid == 0) g_part[blockIdx.x] = s[0];
}

// pass 2: exclusive scan of the 98 partials (single block of 128)
__global__ void k_scan_top() {
    __shared__ int s[128];
    int tid = threadIdx.x;
    s[tid] = (tid < SCAN_BLOCKS) ? g_part[tid] : 0;
    __syncthreads();
    for (int off = 1; off < 128; off <<= 1) {
        int t = (tid >= off) ? s[tid - off] : 0;
        __syncthreads();
        s[tid] += t;
        __syncthreads();
    }
    if (tid < SCAN_BLOCKS) g_part[tid] = (tid == 0) ? 0 : s[tid - 1];
    if (tid == 127) g_rowptr[M_ITEMS] = s[127];  // grand total
}

// pass 3: per-block exclusive scan + global offset; write rowptr & pos
__global__ void k_scan_final() {
    __shared__ int s[256];
    int tid  = threadIdx.x;
    int idx0 = blockIdx.x * SCAN_CHUNK + tid * 4;  // 4 consecutive per thread
    int c[4];
    #pragma unroll
    for (int i = 0; i < 4; i++) {
        int idx = idx0 + i;
        c[i] = (idx < M_ITEMS) ? g_cnt[idx] : 0;
    }
    s[tid] = c[0] + c[1] + c[2] + c[3];
    __syncthreads();
    for (int off = 1; off < 256; off <<= 1) {
        int t = (tid >= off) ? s[tid - off] : 0;
        __syncthreads();
        s[tid] += t;
        __syncthreads();
    }
    int run = g_part[blockIdx.x] + ((tid == 0) ? 0 : s[tid - 1]);
    #pragma unroll
    for (int i = 0; i < 4; i++) {
        int idx = idx0 + i;
        if (idx < M_ITEMS) {
            g_rowptr[idx] = run;
            g_pos[idx]    = run;
            run += c[i];
        }
    }
}

// scatter edges into CSR order, packed (dst, val)
__global__ void k_scatter(const int* __restrict__ src, const int* __restrict__ dst,
                          const float* __restrict__ val, int n) {
    int e = blockIdx.x * blockDim.x + threadIdx.x;
    if (e >= n) return;
    int s = __ldg(src + e);
    int p = atomicAdd(&g_pos[s], 1);
    g_epack[p] = make_int2(__ldg(dst + e), __float_as_int(__ldg(val + e)));
}

// Pull-based item-item SpMM layer, one warp per row, register accumulation.
// y[row] = att[layer] * sum_e val_e * x[dst_e];  g_sum[row] += y[row].
__global__ void k_spmm_pull(const float* __restrict__ x, float* __restrict__ y,
                            const float* __restrict__ att, int layer) {
    int row  = blockIdx.x * (blockDim.x >> 5) + (threadIdx.x >> 5);
    int lane = threadIdx.x & 31;
    if (row >= M_ITEMS) return;

    int beg = g_rowptr[row];
    int end = g_rowptr[row + 1];

    float2 acc = make_float2(0.0f, 0.0f);
    #pragma unroll 4
    for (int e = beg; e < end; e++) {
        int2  ed = __ldg(&g_epack[e]);          // single 8B warp-broadcast load
        float v  = __int_as_float(ed.y);
        float2 xv = __ldg((const float2*)x + (long)ed.x * 32 + lane);
        acc.x = fmaf(v, xv.x, acc.x);
        acc.y = fmaf(v, xv.y, acc.y);
    }
    float a = __ldg(att + layer);
    acc.x *= a; acc.y *= a;

    long o = (long)row * 32 + lane;
    if (y) ((float2*)y)[o] = acc;
    float2* sp = (float2*)g_sum + o;
    float2 sv = *sp;
    sv.x += acc.x; sv.y += acc.y;
    *sp = sv;
}

// user-item push SpMM, filtered to batch users:
// g_users[src] += (val * 0.25) * g_sum[dst]   (only if src is in the batch)
__global__ void k_spmm_ui(const int* __restrict__ src, const int* __restrict__ dst,
                          const float* __restrict__ val, int nedges) {
    long t = (long)blockIdx.x * blockDim.x + threadIdx.x;
    int e    = (int)(t >> 4);
    int lane = (int)(t & 15);
    if (e >= nedges) return;

    int s = __ldg(src + e);
    if (!g_uflag[s]) return;  // ~92% of edges exit here

    int   d = __ldg(dst + e);
    float v = __ldg(val + e) * 0.25f;

    float4 xv = __ldg((const float4*)g_sum + (long)d * 16 + lane);
    float4 r  = make_float4(xv.x * v, xv.y * v, xv.z * v, xv.w * v);
    red_add_f4((float4*)g_users + (long)s * 16 + lane, r);
}

// gamma[b] = dot(g_users[u], 0.25 * g_sum[i]); one warp per pair
__global__ void k_dot(const int* __restrict__ users, const int* __restrict__ items,
                      float* __restrict__ out, int nb) {
    int w    = (blockIdx.x * blockDim.x + threadIdx.x) >> 5;
    int lane = threadIdx.x & 31;
    if (w >= nb) return;

    int u = __ldg(users + w);
    int i = __ldg(items + w);

    float2 a = __ldg((const float2*)g_users + (long)u * 32 + lane);
    float2 b = __ldg((const float2*)g_sum   + (long)i * 32 + lane);
    float p = a.x * b.x + a.y * b.y;

    #pragma unroll
    for (int o = 16; o; o >>= 1) p += __shfl_xor_sync(0xFFFFFFFFu, p, o);

    if (lane == 0) out[w] = 0.25f * p;
}

extern "C" void kernel_launch(void* const* d_in, const int* in_sizes, int n_in,
                              void* d_out, int out_size) {
    const int*   users  = (const int*)d_in[0];
    const int*   items  = (const int*)d_in[1];
    const int*   ii_src = (const int*)d_in[2];
    const int*   ii_dst = (const int*)d_in[3];
    const float* ii_val = (const float*)d_in[4];
    const int*   ui_src = (const int*)d_in[5];
    const int*   ui_dst = (const int*)d_in[6];
    const float* ui_val = (const float*)d_in[7];
    const float* emb    = (const float*)d_in[8];
    const float* att    = (const float*)d_in[9];

    const int Eii = in_sizes[2];
    const int Eui = in_sizes[5];
    const int Bp  = in_sizes[0];

    const int TPB = 256;
    const int nbGrid  = (NB + TPB - 1) / TPB;
    const int eiiGrid = (Eii + TPB - 1) / TPB;
    const int uiGrid  = (int)(((long)Eui * 16 + TPB - 1) / TPB);
    const int rowGrid = (M_ITEMS + (TPB / 32) - 1) / (TPB / 32);

    float *bufA, *bufB;
    cudaGetSymbolAddress((void**)&bufA, g_bufA);
    cudaGetSymbolAddress((void**)&bufB, g_bufB);

    // init + batch-user flags
    k_init<<<nbGrid, TPB>>>(emb);
    k_flag<<<(Bp + TPB - 1) / TPB, TPB>>>(users, Bp);

    // build item-item CSR (histogram -> 3-pass scan -> scatter)
    k_hist      <<<eiiGrid, TPB>>>(ii_src, Eii);
    k_scan_part <<<SCAN_BLOCKS, 256>>>();
    k_scan_top  <<<1, 128>>>();
    k_scan_final<<<SCAN_BLOCKS, 256>>>();
    k_scatter   <<<eiiGrid, TPB>>>(ii_src, ii_dst, ii_val, Eii);

    // 3 pull-based LightGCN layers (sum-accumulate fused into epilogue)
    k_spmm_pull<<<rowGrid, TPB>>>(emb,  bufA, att, 0);
    k_spmm_pull<<<rowGrid, TPB>>>(bufA, bufB, att, 1);
    k_spmm_pull<<<rowGrid, TPB>>>(bufB, nullptr, att, 2);

    // user aggregation, filtered to batch users (0.25 mean folded in)
    k_spmm_ui<<<uiGrid, TPB>>>(ui_src, ui_dst, ui_val, Eui);

    // final per-pair dots
    k_dot<<<(Bp * 32 + TPB - 1) / TPB, TPB>>>(users, items, (float*)d_out, Bp);
}

// round 5
// speedup vs baseline: 2.0478x; 1.1148x over previous
#include <cuda_runtime.h>
#include <cuda_fp16.h>

// Problem constants (fixed by the reference)
#define M_ITEMS 100000
#define N_USERS 50000
#define DIM     64
#define NB      (M_ITEMS * DIM)   // 6,400,000 floats
#define NU      (N_USERS * DIM)   // 3,200,000 floats
#define E_II_MAX 3200000

#define SCAN_CHUNK  1024
#define SCAN_BLOCKS ((M_ITEMS + SCAN_CHUNK - 1) / SCAN_CHUNK)  // 98

// Static device scratch (no allocations allowed)
__device__ __half2 g_h0[NB / 2];        // half layer buffer (emb, then e2)
__device__ __half2 g_h1[NB / 2];        // half layer buffer (e1)
__device__ float g_sum[NB];             // running fp32 sum of layer embeddings
__device__ float g_users[NU];           // all_users (0.25 mean folded into ui spmm)
__device__ int   g_cnt[M_ITEMS];        // per-row edge counts (histogram)
__device__ int   g_rowptr[M_ITEMS + 1]; // CSR row pointers
__device__ int   g_pos[M_ITEMS];        // scatter fill cursors
__device__ int2  g_epack[E_II_MAX];     // CSR: packed (dst, val-bits) per edge
__device__ int   g_part[SCAN_BLOCKS];   // scan partials
__device__ unsigned char g_uflag[N_USERS]; // batch-user membership flags

// Vector reduction-add to global (sm_90+)
__device__ __forceinline__ void red_add_f4(float4* addr, float4 v) {
    asm volatile("red.global.add.v4.f32 [%0], {%1, %2, %3, %4};"
                 :: "l"(addr), "f"(v.x), "f"(v.y), "f"(v.z), "f"(v.w)
                 : "memory");
}

// init: g_sum = emb (fp32), g_h0 = half(emb), zero users/counters/flags
__global__ void k_init(const float* __restrict__ emb) {
    int i = blockIdx.x * blockDim.x + threadIdx.x;
    if (i < NB / 2) {
        float2 v = ((const float2*)emb)[i];
        ((float2*)g_sum)[i] = v;
        g_h0[i] = __floats2half2_rn(v.x, v.y);
    }
    if (i < NU) g_users[i] = 0.0f;
    if (i < M_ITEMS) g_cnt[i] = 0;
    if (i < N_USERS) g_uflag[i] = 0;
}

// flag the users that appear in the batch
__global__ void k_flag(const int* __restrict__ users, int nb) {
    int i = blockIdx.x * blockDim.x + threadIdx.x;
    if (i < nb) g_uflag[users[i]] = 1;
}

// histogram of edge sources
__global__ void k_hist(const int* __restrict__ src, int n) {
    int e = blockIdx.x * blockDim.x + threadIdx.x;
    if (e < n) atomicAdd(&g_cnt[__ldg(src + e)], 1);
}

// ---- 3-pass parallel exclusive scan over g_cnt -> g_rowptr, g_pos ----

__global__ void k_scan_part() {
    __shared__ int s[256];
    int tid  = threadIdx.x;
    int base = blockIdx.x * SCAN_CHUNK;
    int sum = 0;
    #pragma unroll
    for (int i = 0; i < 4; i++) {
        int idx = base + tid + i * 256;
        if (idx < M_ITEMS) sum += g_cnt[idx];
    }
    s[tid] = sum;
    __syncthreads();
    for (int off = 128; off; off >>= 1) {
        if (tid < off) s[tid] += s[tid + off];
        __syncthreads();
    }
    if (tid == 0) g_part[blockIdx.x] = s[0];
}

__global__ void k_scan_top() {
    __shared__ int s[128];
    int tid = threadIdx.x;
    s[tid] = (tid < SCAN_BLOCKS) ? g_part[tid] : 0;
    __syncthreads();
    for (int off = 1; off < 128; off <<= 1) {
        int t = (tid >= off) ? s[tid - off] : 0;
        __syncthreads();
        s[tid] += t;
        __syncthreads();
    }
    if (tid < SCAN_BLOCKS) g_part[tid] = (tid == 0) ? 0 : s[tid - 1];
    if (tid == 127) g_rowptr[M_ITEMS] = s[127];
}

__global__ void k_scan_final() {
    __shared__ int s[256];
    int tid  = threadIdx.x;
    int idx0 = blockIdx.x * SCAN_CHUNK + tid * 4;
    int c[4];
    #pragma unroll
    for (int i = 0; i < 4; i++) {
        int idx = idx0 + i;
        c[i] = (idx < M_ITEMS) ? g_cnt[idx] : 0;
    }
    s[tid] = c[0] + c[1] + c[2] + c[3];
    __syncthreads();
    for (int off = 1; off < 256; off <<= 1) {
        int t = (tid >= off) ? s[tid - off] : 0;
        __syncthreads();
        s[tid] += t;
        __syncthreads();
    }
    int run = g_part[blockIdx.x] + ((tid == 0) ? 0 : s[tid - 1]);
    #pragma unroll
    for (int i = 0; i < 4; i++) {
        int idx = idx0 + i;
        if (idx < M_ITEMS) {
            g_rowptr[idx] = run;
            g_pos[idx]    = run;
            run += c[i];
        }
    }
}

// scatter edges into CSR order, packed (dst, val)
__global__ void k_scatter(const int* __restrict__ src, const int* __restrict__ dst,
                          const float* __restrict__ val, int n) {
    int e = blockIdx.x * blockDim.x + threadIdx.x;
    if (e >= n) return;
    int s = __ldg(src + e);
    int p = atomicAdd(&g_pos[s], 1);
    g_epack[p] = make_int2(__ldg(dst + e), __float_as_int(__ldg(val + e)));
}

// Pull-based item-item SpMM layer, one warp per row, fp32 register accumulation
// over half2 gathered operands (128B/row gather instead of 256B).
// g_sum[row] += att*Σ; if yh, also store half2 result for the next layer.
__global__ void k_spmm_pull(const __half2* __restrict__ x, __half2* __restrict__ yh,
                            const float* __restrict__ att, int layer) {
    int row  = blockIdx.x * (blockDim.x >> 5) + (threadIdx.x >> 5);
    int lane = threadIdx.x & 31;
    if (row >= M_ITEMS) return;

    int beg = g_rowptr[row];
    int end = g_rowptr[row + 1];

    float accx = 0.0f, accy = 0.0f;
    #pragma unroll 8
    for (int e = beg; e < end; e++) {
        int2  ed = __ldg(&g_epack[e]);          // 8B warp-broadcast load
        float v  = __int_as_float(ed.y);
        float2 xv = __half22float2(__ldg(x + (long)ed.x * 32 + lane));
        accx = fmaf(v, xv.x, accx);
        accy = fmaf(v, xv.y, accy);
    }
    float a = __ldg(att + layer);
    accx *= a; accy *= a;

    long o = (long)row * 32 + lane;
    if (yh) yh[o] = __floats2half2_rn(accx, accy);
    float2* sp = (float2*)g_sum + o;
    float2 sv = *sp;
    sv.x += accx; sv.y += accy;
    *sp = sv;
}

// user-item push SpMM, filtered to batch users (fp32 exact):
// g_users[src] += (val * 0.25) * g_sum[dst]
__global__ void k_spmm_ui(const int* __restrict__ src, const int* __restrict__ dst,
                          const float* __restrict__ val, int nedges) {
    long t = (long)blockIdx.x * blockDim.x + threadIdx.x;
    int e    = (int)(t >> 4);
    int lane = (int)(t & 15);
    if (e >= nedges) return;

    int s = __ldg(src + e);
    if (!g_uflag[s]) return;  // ~92% of edges exit here

    int   d = __ldg(dst + e);
    float v = __ldg(val + e) * 0.25f;

    float4 xv = __ldg((const float4*)g_sum + (long)d * 16 + lane);
    float4 r  = make_float4(xv.x * v, xv.y * v, xv.z * v, xv.w * v);
    red_add_f4((float4*)g_users + (long)s * 16 + lane, r);
}

// gamma[b] = dot(g_users[u], 0.25 * g_sum[i]); one warp per pair
__global__ void k_dot(const int* __restrict__ users, const int* __restrict__ items,
                      float* __restrict__ out, int nb) {
    int w    = (blockIdx.x * blockDim.x + threadIdx.x) >> 5;
    int lane = threadIdx.x & 31;
    if (w >= nb) return;

    int u = __ldg(users + w);
    int i = __ldg(items + w);

    float2 a = __ldg((const float2*)g_users + (long)u * 32 + lane);
    float2 b = __ldg((const float2*)g_sum   + (long)i * 32 + lane);
    float p = a.x * b.x + a.y * b.y;

    #pragma unroll
    for (int o = 16; o; o >>= 1) p += __shfl_xor_sync(0xFFFFFFFFu, p, o);

    if (lane == 0) out[w] = 0.25f * p;
}

extern "C" void kernel_launch(void* const* d_in, const int* in_sizes, int n_in,
                              void* d_out, int out_size) {
    const int*   users  = (const int*)d_in[0];
    const int*   items  = (const int*)d_in[1];
    const int*   ii_src = (const int*)d_in[2];
    const int*   ii_dst = (const int*)d_in[3];
    const float* ii_val = (const float*)d_in[4];
    const int*   ui_src = (const int*)d_in[5];
    const int*   ui_dst = (const int*)d_in[6];
    const float* ui_val = (const float*)d_in[7];
    const float* emb    = (const float*)d_in[8];
    const float* att    = (const float*)d_in[9];

    const int Eii = in_sizes[2];
    const int Eui = in_sizes[5];
    const int Bp  = in_sizes[0];

    const int TPB = 256;
    const int nbGrid  = (NB + TPB - 1) / TPB;   // covers NB/2 half2 + all zero-fills
    const int eiiGrid = (Eii + TPB - 1) / TPB;
    const int uiGrid  = (int)(((long)Eui * 16 + TPB - 1) / TPB);
    const int rowGrid = (M_ITEMS + (TPB / 32) - 1) / (TPB / 32);

    __half2 *h0, *h1;
    cudaGetSymbolAddress((void**)&h0, g_h0);
    cudaGetSymbolAddress((void**)&h1, g_h1);

    // init + batch-user flags
    k_init<<<nbGrid, TPB>>>(emb);
    k_flag<<<(Bp + TPB - 1) / TPB, TPB>>>(users, Bp);

    // build item-item CSR (histogram -> 3-pass scan -> scatter)
    k_hist      <<<eiiGrid, TPB>>>(ii_src, Eii);
    k_scan_part <<<SCAN_BLOCKS, 256>>>();
    k_scan_top  <<<1, 128>>>();
    k_scan_final<<<SCAN_BLOCKS, 256>>>();
    k_scatter   <<<eiiGrid, TPB>>>(ii_src, ii_dst, ii_val, Eii);

    // 3 pull-based LightGCN layers over half2 operands (sum fused, fp32 acc)
    k_spmm_pull<<<rowGrid, TPB>>>(h0, h1,      att, 0);  // emb  -> e1
    k_spmm_pull<<<rowGrid, TPB>>>(h1, h0,      att, 1);  // e1   -> e2 (overwrite emb-half)
    k_spmm_pull<<<rowGrid, TPB>>>(h0, nullptr, att, 2);  // e2   -> (sum only)

    // user aggregation, filtered to batch users (0.25 mean folded in)
    k_spmm_ui<<<uiGrid, TPB>>>(ui_src, ui_dst, ui_val, Eui);

    // final per-pair dots
    k_dot<<<(Bp * 32 + TPB - 1) / TPB, TPB>>>(users, items, (float*)d_out, Bp);
}

// round 7
// speedup vs baseline: 2.2088x; 1.0786x over previous
#include <cuda_runtime.h>
#include <cuda_fp16.h>
#include <cstdint>

// Problem constants (fixed by the reference)
#define M_ITEMS 100000
#define N_USERS 50000
#define DIM     64
#define NB      (M_ITEMS * DIM)   // 6,400,000 floats
#define NU      (N_USERS * DIM)   // 3,200,000 floats
#define E_II_MAX 3200000

#define SCAN_CHUNK  1024
#define SCAN_BLOCKS ((M_ITEMS + SCAN_CHUNK - 1) / SCAN_CHUNK)  // 98

// Static device scratch (no allocations allowed)
__device__ __half2 g_h0[NB / 2];        // half layer buffer (emb, then e2)
__device__ __half2 g_h1[NB / 2];        // half layer buffer (e1)
__device__ float g_sum[NB];             // running fp32 sum of layer embeddings
__device__ float g_users[NU];           // all_users (0.25 mean folded into ui spmm)
__device__ int   g_cnt[M_ITEMS];        // per-row counts (zeroed by k_scan_final each run)
__device__ int   g_rowptr[M_ITEMS + 1]; // CSR row pointers
__device__ int   g_pos[M_ITEMS];        // scatter fill cursors
__device__ int2  g_epack[E_II_MAX];     // CSR: packed (dst, val-bits) per edge
__device__ int   g_part[SCAN_BLOCKS];   // scan partials
__device__ unsigned char g_uflag[N_USERS]; // batch-user flags (set-only, idempotent)

// Vector reduction-add to global (sm_90+)
__device__ __forceinline__ void red_add_f4(float4* addr, float4 v) {
    asm volatile("red.global.add.v4.f32 [%0], {%1, %2, %3, %4};"
                 :: "l"(addr), "f"(v.x), "f"(v.y), "f"(v.z), "f"(v.w)
                 : "memory");
}

// Fused: g_sum=emb, g_h0=half(emb), zero g_users, flag batch users, histogram.
// g_cnt is guaranteed zero on entry: static init on first run, re-zeroed by
// k_scan_final on every run. g_uflag is set-only (same users every run).
__global__ void k_pre(const float* __restrict__ emb, const int* __restrict__ users,
                      int nusers, const int* __restrict__ src, int ne) {
    int i = blockIdx.x * blockDim.x + threadIdx.x;
    if (i < NB / 2) {
        float2 v = ((const float2*)emb)[i];
        ((float2*)g_sum)[i] = v;
        g_h0[i] = __floats2half2_rn(v.x, v.y);
    }
    if (i < NU) g_users[i] = 0.0f;
    if (i < nusers) g_uflag[__ldg(users + i)] = 1;
    if (i < ne) atomicAdd(&g_cnt[__ldg(src + i)], 1);
}

// pass 1: per-1024-chunk sums
__global__ void k_scan_part() {
    __shared__ int s[256];
    int tid  = threadIdx.x;
    int base = blockIdx.x * SCAN_CHUNK;
    int sum = 0;
    #pragma unroll
    for (int i = 0; i < 4; i++) {
        int idx = base + tid + i * 256;
        if (idx < M_ITEMS) sum += g_cnt[idx];
    }
    s[tid] = sum;
    __syncthreads();
    for (int off = 128; off; off >>= 1) {
        if (tid < off) s[tid] += s[tid + off];
        __syncthreads();
    }
    if (tid == 0) g_part[blockIdx.x] = s[0];
}

// pass 2 (fused top+final): every block scans the 98 partials itself, then does
// its local exclusive scan, writes rowptr/pos, and zeroes g_cnt for next run.
__global__ void k_scan_final() {
    __shared__ int s[256];
    __shared__ int spart[128];
    int tid = threadIdx.x;

    if (tid < 128) spart[tid] = (tid < SCAN_BLOCKS) ? g_part[tid] : 0;
    __syncthreads();
    for (int off = 1; off < 128; off <<= 1) {
        int t = (tid < 128 && tid >= off) ? spart[tid - off] : 0;
        __syncthreads();
        if (tid < 128) spart[tid] += t;
        __syncthreads();
    }
    int blockOff = (blockIdx.x == 0) ? 0 : spart[blockIdx.x - 1];

    int idx0 = blockIdx.x * SCAN_CHUNK + tid * 4;
    int c[4];
    #pragma unroll
    for (int i = 0; i < 4; i++) {
        int idx = idx0 + i;
        c[i] = (idx < M_ITEMS) ? g_cnt[idx] : 0;
    }
    s[tid] = c[0] + c[1] + c[2] + c[3];
    __syncthreads();
    for (int off = 1; off < 256; off <<= 1) {
        int t = (tid >= off) ? s[tid - off] : 0;
        __syncthreads();
        s[tid] += t;
        __syncthreads();
    }
    int run = blockOff + ((tid == 0) ? 0 : s[tid - 1]);
    #pragma unroll
    for (int i = 0; i < 4; i++) {
        int idx = idx0 + i;
        if (idx < M_ITEMS) {
            g_rowptr[idx] = run;
            g_pos[idx]    = run;
            g_cnt[idx]    = 0;        // reset for next graph replay
            run += c[i];
        }
    }
    if (blockIdx.x == SCAN_BLOCKS - 1 && tid == 0)
        g_rowptr[M_ITEMS] = spart[SCAN_BLOCKS - 1];
}

// scatter edges into CSR order, packed (dst, val)
__global__ void k_scatter(const int* __restrict__ src, const int* __restrict__ dst,
                          const float* __restrict__ val, int n) {
    int e = blockIdx.x * blockDim.x + threadIdx.x;
    if (e >= n) return;
    int s = __ldg(src + e);
    int p = atomicAdd(&g_pos[s], 1);
    g_epack[p] = make_int2(__ldg(dst + e), __float_as_int(__ldg(val + e)));
}

// Pull SpMM, one warp per row, TWO edges per iteration (16 lanes/edge).
// Lane group sub = lane>>4 handles edge e+sub; lane16 covers 4 dims via 8B load.
// fp32 accumulation; final cross-half combine via shfl_xor(16).
__global__ void k_spmm_pull(const __half2* __restrict__ x, __half2* __restrict__ yh,
                            const float* __restrict__ att, int layer) {
    int row  = blockIdx.x * (blockDim.x >> 5) + (threadIdx.x >> 5);
    int lane = threadIdx.x & 31;
    if (row >= M_ITEMS) return;
    int lane16 = lane & 15;
    int sub    = lane >> 4;

    int beg = g_rowptr[row];
    int end = g_rowptr[row + 1];

    float4 acc = make_float4(0.0f, 0.0f, 0.0f, 0.0f);
    #pragma unroll 4
    for (int e = beg; e < end; e += 2) {
        int  idx = e + sub;
        bool ok  = idx < end;
        int2 ed  = __ldg(&g_epack[ok ? idx : beg]);
        float v  = ok ? __int_as_float(ed.y) : 0.0f;
        uint2 raw = __ldg((const uint2*)x + (long)ed.x * 16 + lane16);
        float2 f0 = __half22float2(*reinterpret_cast<__half2*>(&raw.x));
        float2 f1 = __half22float2(*reinterpret_cast<__half2*>(&raw.y));
        acc.x = fmaf(v, f0.x, acc.x);
        acc.y = fmaf(v, f0.y, acc.y);
        acc.z = fmaf(v, f1.x, acc.z);
        acc.w = fmaf(v, f1.y, acc.w);
    }
    acc.x += __shfl_xor_sync(0xFFFFFFFFu, acc.x, 16);
    acc.y += __shfl_xor_sync(0xFFFFFFFFu, acc.y, 16);
    acc.z += __shfl_xor_sync(0xFFFFFFFFu, acc.z, 16);
    acc.w += __shfl_xor_sync(0xFFFFFFFFu, acc.w, 16);

    if (sub == 0) {
        float a = __ldg(att + layer);
        acc.x *= a; acc.y *= a; acc.z *= a; acc.w *= a;
        long o = (long)row * 16 + lane16;
        if (yh) {
            __half2 p0 = __floats2half2_rn(acc.x, acc.y);
            __half2 p1 = __floats2half2_rn(acc.z, acc.w);
            uint2 hp;
            hp.x = *reinterpret_cast<unsigned int*>(&p0);
            hp.y = *reinterpret_cast<unsigned int*>(&p1);
            ((uint2*)yh)[o] = hp;
        }
        float4* sp = (float4*)g_sum + o;
        float4 sv = *sp;
        sv.x += acc.x; sv.y += acc.y; sv.z += acc.z; sv.w += acc.w;
        *sp = sv;
    }
}

// user-item push SpMM, filtered to batch users (fp32 exact):
// g_users[src] += (val * 0.25) * g_sum[dst]
__global__ void k_spmm_ui(const int* __restrict__ src, const int* __restrict__ dst,
                          const float* __restrict__ val, int nedges) {
    long t = (long)blockIdx.x * blockDim.x + threadIdx.x;
    int e    = (int)(t >> 4);
    int lane = (int)(t & 15);
    if (e >= nedges) return;

    int s = __ldg(src + e);
    if (!g_uflag[s]) return;  // ~92% of edges exit here

    int   d = __ldg(dst + e);
    float v = __ldg(val + e) * 0.25f;

    float4 xv = __ldg((const float4*)g_sum + (long)d * 16 + lane);
    float4 r  = make_float4(xv.x * v, xv.y * v, xv.z * v, xv.w * v);
    red_add_f4((float4*)g_users + (long)s * 16 + lane, r);
}

// gamma[b] = dot(g_users[u], 0.25 * g_sum[i]); one warp per pair
__global__ void k_dot(const int* __restrict__ users, const int* __restrict__ items,
                      float* __restrict__ out, int nb) {
    int w    = (blockIdx.x * blockDim.x + threadIdx.x) >> 5;
    int lane = threadIdx.x & 31;
    if (w >= nb) return;

    int u = __ldg(users + w);
    int i = __ldg(items + w);

    float2 a = __ldg((const float2*)g_users + (long)u * 32 + lane);
    float2 b = __ldg((const float2*)g_sum   + (long)i * 32 + lane);
    float p = a.x * b.x + a.y * b.y;

    #pragma unroll
    for (int o = 16; o; o >>= 1) p += __shfl_xor_sync(0xFFFFFFFFu, p, o);

    if (lane == 0) out[w] = 0.25f * p;
}

extern "C" void kernel_launch(void* const* d_in, const int* in_sizes, int n_in,
                              void* d_out, int out_size) {
    const int*   users  = (const int*)d_in[0];
    const int*   items  = (const int*)d_in[1];
    const int*   ii_src = (const int*)d_in[2];
    const int*   ii_dst = (const int*)d_in[3];
    const float* ii_val = (const float*)d_in[4];
    const int*   ui_src = (const int*)d_in[5];
    const int*   ui_dst = (const int*)d_in[6];
    const float* ui_val = (const float*)d_in[7];
    const float* emb    = (const float*)d_in[8];
    const float* att    = (const float*)d_in[9];

    const int Eii = in_sizes[2];
    const int Eui = in_sizes[5];
    const int Bp  = in_sizes[0];

    const int TPB = 256;
    int preN   = (NB / 2 > Eii) ? NB / 2 : Eii;
    const int preGrid = (preN + TPB - 1) / TPB;
    const int eiiGrid = (Eii + TPB - 1) / TPB;
    const int uiGrid  = (int)(((long)Eui * 16 + TPB - 1) / TPB);
    const int rowGrid = (M_ITEMS + (TPB / 32) - 1) / (TPB / 32);

    __half2 *h0, *h1;
    cudaGetSymbolAddress((void**)&h0, g_h0);
    cudaGetSymbolAddress((void**)&h1, g_h1);

    // 0: fused init + flag + histogram
    k_pre<<<preGrid, TPB>>>(emb, users, Bp, ii_src, Eii);
    // 1-2: scan (part sums, then fused top+final which also re-zeroes g_cnt)
    k_scan_part <<<SCAN_BLOCKS, 256>>>();
    k_scan_final<<<SCAN_BLOCKS, 256>>>();
    // 3: scatter into CSR  (this is the launch ncu will profile)
    k_scatter<<<eiiGrid, TPB>>>(ii_src, ii_dst, ii_val, Eii);

    // 4-6: pull-based LightGCN layers (sum fused, fp32 acc over half2 operands)
    k_spmm_pull<<<rowGrid, TPB>>>(h0, h1,      att, 0);  // emb -> e1
    k_spmm_pull<<<rowGrid, TPB>>>(h1, h0,      att, 1);  // e1  -> e2
    k_spmm_pull<<<rowGrid, TPB>>>(h0, nullptr, att, 2);  // e2  -> (sum only)

    // 7: user aggregation, filtered to batch users (0.25 mean folded in)
    k_spmm_ui<<<uiGrid, TPB>>>(ui_src, ui_dst, ui_val, Eui);

    // 8: final per-pair dots
    k_dot<<<(Bp * 32 + TPB - 1) / TPB, TPB>>>(users, items, (float*)d_out, Bp);
}